// round 9
// baseline (speedup 1.0000x reference)
#include <cuda_runtime.h>

// PCEN: M = EMA(data, s=0.5) along T;  out = (x/(eps+M)^alpha + delta)^r - delta^r
// data: [F=1024, T=50000] fp32 row-major. alpha/r/delta: 1-elem fp32 arrays.
//
// R9: persistent warp chains + double-buffered register prefetch.
// Stage = 4 k-iters x 32 lanes x float4 (=512 samples), coalesced.
// Per float4 the EMA is affine: M -> M/16 + W, W = sum_e 0.5^(4-e) x_e.
// Truncated Kogge-Stone scan (shifts 1,2,4; lambda=1/16) covers 32 samples;
// cross-k/stage carry = S(lane31) (older terms decay by 16^-32 -> 0 in fp32).
// Each warp owns CH=7 consecutive stages of one row; while stage g is
// computed, stage g+1's loads are in flight; g+2 is issued right after g is
// consumed -> reads pending ~100% of warp lifetime (R8 was ~43%).
// Halo: one predicated float4 per CHAIN (lanes 24-31). No smem.

#define BLOCK 256
#define WARPS (BLOCK / 32)
#define KPS   4                 // k-iterations per stage
#define ST4   (KPS * 32)        // 128 float4 per stage
#define CH    7                 // stages per warp chain (3584 samples)

__device__ __forceinline__ float ex2a(float x)  { float y; asm("ex2.approx.f32 %0, %1;"  : "=f"(y) : "f"(x)); return y; }
__device__ __forceinline__ float lg2a(float x)  { float y; asm("lg2.approx.f32 %0, %1;"  : "=f"(y) : "f"(x)); return y; }
__device__ __forceinline__ float sqrta(float x) { float y; asm("sqrt.approx.f32 %0, %1;" : "=f"(y) : "f"(x)); return y; }

__device__ __forceinline__ float pcen_g(float x, float& M, float alpha,
                                        float r, float delta, float dr)
{
    M = 0.5f * (M + x);
    const float inv = ex2a(-alpha * lg2a(M + 1e-6f));
    const float y   = fmaf(x, inv, delta);
    return ex2a(r * lg2a(y)) - dr;
}

__device__ __forceinline__ float pcen_h(float x, float& M, float alpha,
                                        float delta, float dr)
{
    M = 0.5f * (M + x);
    const float inv = ex2a(-alpha * lg2a(M + 1e-6f));
    const float y   = fmaf(x, inv, delta);
    return sqrta(y) - dr;
}

// per-lane affine term of one float4: W = x0/16 + x1/8 + x2/4 + x3/2
__device__ __forceinline__ float wterm(const float4& x)
{
    float W = x.w * 0.5f;
    W = fmaf(x.z, 0.25f,   W);
    W = fmaf(x.y, 0.125f,  W);
    W = fmaf(x.x, 0.0625f, W);
    return W;
}

// truncated decayed inclusive scan, lambda = 1/16, coverage 8 lanes = 32 samples
__device__ __forceinline__ float dscan(float W, int lane)
{
    float S = W, t;
    t = __shfl_up_sync(0xffffffffu, S, 1); if (lane >= 1) S = fmaf(t, 0.0625f,           S);
    t = __shfl_up_sync(0xffffffffu, S, 2); if (lane >= 2) S = fmaf(t, 3.90625e-3f,       S);
    t = __shfl_up_sync(0xffffffffu, S, 4); if (lane >= 4) S = fmaf(t, 1.52587890625e-5f, S);
    return S;
}

template<bool FULL>
__device__ __forceinline__ void load_stage(float4 (&xs)[KPS], int sbase, int lane,
                                           const float4* __restrict__ data4,
                                           int rowBase4, int T4)
{
    #pragma unroll
    for (int k = 0; k < KPS; ++k) {
        const int idx = sbase + k * 32 + lane;
        if (FULL) {
            xs[k] = data4[rowBase4 + idx];
        } else {
            xs[k] = make_float4(0.f, 0.f, 0.f, 0.f);
            if (idx < T4) xs[k] = data4[rowBase4 + idx];
        }
    }
}

template<bool FULL, bool RHALF>
__device__ __forceinline__ void stage_compute(const float4 (&xs)[KPS], float& carry,
                                              float fl, int lane, int sbase,
                                              int rowBase4, int T4,
                                              float alpha, float r, float delta, float dr,
                                              float4* __restrict__ out4)
{
    #pragma unroll
    for (int k = 0; k < KPS; ++k) {
        const float S = dscan(wterm(xs[k]), lane);
        const float t = __shfl_up_sync(0xffffffffu, S, 1);
        float M = fmaf(carry, fl, (lane != 0) ? t : 0.0f);   // state entering this float4
        carry = __shfl_sync(0xffffffffu, S, 31);

        const int idx = sbase + k * 32 + lane;
        if (FULL || idx < T4) {
            const float4 x = xs[k];
            float4 res;
            if (RHALF) {
                res.x = pcen_h(x.x, M, alpha, delta, dr);
                res.y = pcen_h(x.y, M, alpha, delta, dr);
                res.z = pcen_h(x.z, M, alpha, delta, dr);
                res.w = pcen_h(x.w, M, alpha, delta, dr);
            } else {
                res.x = pcen_g(x.x, M, alpha, r, delta, dr);
                res.y = pcen_g(x.y, M, alpha, r, delta, dr);
                res.z = pcen_g(x.z, M, alpha, r, delta, dr);
                res.w = pcen_g(x.w, M, alpha, r, delta, dr);
            }
            out4[rowBase4 + idx] = res;
        }
    }
}

template<bool FULL, bool RHALF>
__device__ __forceinline__ void run_chain(const float4* __restrict__ data4,
                                          float4* __restrict__ out4,
                                          int cbase, int lane, int rowBase4, int T4,
                                          float carry, float fl,
                                          float alpha, float r, float delta, float dr)
{
    float4 A[KPS], B[KPS];
    load_stage<FULL>(A, cbase,        lane, data4, rowBase4, T4);
    load_stage<FULL>(B, cbase + ST4,  lane, data4, rowBase4, T4);

    #pragma unroll
    for (int g = 0; g < CH; g += 2) {
        stage_compute<FULL, RHALF>(A, carry, fl, lane, cbase + g * ST4,
                                   rowBase4, T4, alpha, r, delta, dr, out4);
        if (g + 2 < CH)
            load_stage<FULL>(A, cbase + (g + 2) * ST4, lane, data4, rowBase4, T4);

        if (g + 1 < CH) {
            stage_compute<FULL, RHALF>(B, carry, fl, lane, cbase + (g + 1) * ST4,
                                       rowBase4, T4, alpha, r, delta, dr, out4);
            if (g + 3 < CH)
                load_stage<FULL>(B, cbase + (g + 3) * ST4, lane, data4, rowBase4, T4);
        }
    }
}

__global__ __launch_bounds__(BLOCK, 5)
void pcen_kernel(const float4* __restrict__ data4,
                 const float*  __restrict__ alpha_p,
                 const float*  __restrict__ r_p,
                 const float*  __restrict__ delta_p,
                 float4* __restrict__ out4,
                 int T4, int wpr, int totalW)        // warps per row, total warps
{
    const int lane = threadIdx.x & 31;
    const int gw   = blockIdx.x * WARPS + (threadIdx.x >> 5);
    if (gw >= totalW) return;                        // warp-uniform

    const int row  = gw / wpr;
    const int slot = gw - row * wpr;
    const int rowBase4 = row * T4;                   // int32 safe (< 12.8M)
    const int cbase = slot * (CH * ST4);             // chain base (float4, < T4)

    // ---- halo: 32 samples before the chain (lanes 24-31, one float4) ----
    float4 h = make_float4(0.f, 0.f, 0.f, 0.f);
    const int hidx = cbase - 32 + lane;
    if (lane >= 24 && hidx >= 0) h = data4[rowBase4 + hidx];
    const float carry0 = __shfl_sync(0xffffffffu, dscan(wterm(h), lane), 31);

    const float alpha = *alpha_p;
    const float r     = *r_p;
    const float delta = *delta_p;
    const bool  rhalf = (r == 0.5f);
    const float dr    = rhalf ? sqrta(delta) : ex2a(r * lg2a(delta));
    const float fl    = __uint_as_float((unsigned)(127 - 4 * lane) << 23); // 16^-lane

    const bool full = (cbase + CH * ST4) <= T4;

    if (full) {
        if (rhalf) run_chain<true,  true >(data4, out4, cbase, lane, rowBase4, T4, carry0, fl, alpha, r, delta, dr);
        else       run_chain<true,  false>(data4, out4, cbase, lane, rowBase4, T4, carry0, fl, alpha, r, delta, dr);
    } else {
        if (rhalf) run_chain<false, true >(data4, out4, cbase, lane, rowBase4, T4, carry0, fl, alpha, r, delta, dr);
        else       run_chain<false, false>(data4, out4, cbase, lane, rowBase4, T4, carry0, fl, alpha, r, delta, dr);
    }
}

extern "C" void kernel_launch(void* const* d_in, const int* in_sizes, int n_in,
                              void* d_out, int out_size)
{
    const float4* data4   = (const float4*)d_in[0];
    const float*  alpha_p = (const float*)d_in[1];
    const float*  r_p     = (const float*)d_in[2];
    const float*  delta_p = (const float*)d_in[3];
    float4* out4 = (float4*)d_out;

    const int total = in_sizes[0];
    const int F  = 1024;
    const int T  = total / F;                         // 50000
    const int T4 = T / 4;                             // 12500
    const int chain4 = CH * ST4;                      // 896 float4 per chain
    const int wpr    = (T4 + chain4 - 1) / chain4;    // 14
    const int totalW = F * wpr;                       // 14336
    const int blocks = (totalW + WARPS - 1) / WARPS;  // 1792

    pcen_kernel<<<blocks, BLOCK>>>(data4, alpha_p, r_p, delta_p, out4,
                                   T4, wpr, totalW);
}

// round 10
// speedup vs baseline: 1.1477x; 1.1477x over previous
#include <cuda_runtime.h>

// PCEN: M = EMA(data, s=0.5) along T;  out = (x/(eps+M)^alpha + delta)^r - delta^r
// data: [F=1024, T=50000] fp32 row-major. alpha/r/delta: 1-elem fp32 arrays.
//
// R10 = R8 (burst-load register warp-scan, best known: 64.0us, DRAM 77%)
// with occupancy push: KITER 8->6 (24 reg buffer) + __launch_bounds__(256,6)
// -> 48 warps/SM. Kernel is jointly DRAM(77%)/MUFU(~70%)-bound; more resident
// warps improves overlap of both. FULL/RHALF templated fast paths.
//
// Math: per float4 the EMA is affine M -> M/16 + W, W = sum_e 0.5^(4-e) x_e.
// Truncated Kogge-Stone scan (shifts 1,2,4; lambda=1/16) covers 32 samples;
// carry = S(lane31) chains k-iterations (older terms decay 16^-32 -> 0).
// Halo: one predicated float4 on lanes 24-31 per segment. No smem.

#define BLOCK  256
#define WARPS  (BLOCK / 32)
#define KITER  6
#define SEG4   (KITER * 32)          // 192 float4 per warp segment

__device__ __forceinline__ float ex2a(float x)  { float y; asm("ex2.approx.f32 %0, %1;"  : "=f"(y) : "f"(x)); return y; }
__device__ __forceinline__ float lg2a(float x)  { float y; asm("lg2.approx.f32 %0, %1;"  : "=f"(y) : "f"(x)); return y; }
__device__ __forceinline__ float sqrta(float x) { float y; asm("sqrt.approx.f32 %0, %1;" : "=f"(y) : "f"(x)); return y; }

__device__ __forceinline__ float pcen_g(float x, float& M, float alpha,
                                        float r, float delta, float dr)
{
    M = 0.5f * (M + x);
    const float inv = ex2a(-alpha * lg2a(M + 1e-6f));
    const float y   = fmaf(x, inv, delta);
    return ex2a(r * lg2a(y)) - dr;
}

__device__ __forceinline__ float pcen_h(float x, float& M, float alpha,
                                        float delta, float dr)
{
    M = 0.5f * (M + x);
    const float inv = ex2a(-alpha * lg2a(M + 1e-6f));
    const float y   = fmaf(x, inv, delta);
    return sqrta(y) - dr;
}

// per-lane affine term of one float4: W = x0/16 + x1/8 + x2/4 + x3/2
__device__ __forceinline__ float wterm(const float4& x)
{
    float W = x.w * 0.5f;
    W = fmaf(x.z, 0.25f,   W);
    W = fmaf(x.y, 0.125f,  W);
    W = fmaf(x.x, 0.0625f, W);
    return W;
}

// truncated decayed inclusive scan, lambda = 1/16, coverage 8 lanes = 32 samples
__device__ __forceinline__ float dscan(float W, int lane)
{
    float S = W, t;
    t = __shfl_up_sync(0xffffffffu, S, 1); if (lane >= 1) S = fmaf(t, 0.0625f,           S);
    t = __shfl_up_sync(0xffffffffu, S, 2); if (lane >= 2) S = fmaf(t, 3.90625e-3f,       S);
    t = __shfl_up_sync(0xffffffffu, S, 4); if (lane >= 4) S = fmaf(t, 1.52587890625e-5f, S);
    return S;
}

template<bool FULL, bool RHALF>
__device__ __forceinline__ void do_segment(const float4* __restrict__ data4,
                                           float4* __restrict__ out4,
                                           int base4, int lane, int rowBase4, int T4,
                                           float alpha, float r, float delta, float dr,
                                           float fl)
{
    // ---- burst: all loads in flight at once (MLP = KITER+1) ----
    float4 x[KITER];
    #pragma unroll
    for (int k = 0; k < KITER; ++k) {
        const int idx = base4 + k * 32 + lane;
        if (FULL) {
            x[k] = data4[rowBase4 + idx];
        } else {
            x[k] = make_float4(0.f, 0.f, 0.f, 0.f);
            if (idx < T4) x[k] = data4[rowBase4 + idx];
        }
    }
    float4 h = make_float4(0.f, 0.f, 0.f, 0.f);
    const int hidx = base4 - 32 + lane;              // lanes 24..31: 8 float4 before seg
    if (lane >= 24 && hidx >= 0) h = data4[rowBase4 + hidx];

    float carry = __shfl_sync(0xffffffffu, dscan(wterm(h), lane), 31);

    #pragma unroll
    for (int k = 0; k < KITER; ++k) {
        const float S = dscan(wterm(x[k]), lane);
        const float t = __shfl_up_sync(0xffffffffu, S, 1);
        float M = fmaf(carry, fl, (lane != 0) ? t : 0.0f);
        carry = __shfl_sync(0xffffffffu, S, 31);

        const int idx = base4 + k * 32 + lane;
        if (FULL || idx < T4) {
            float4 res;
            if (RHALF) {
                res.x = pcen_h(x[k].x, M, alpha, delta, dr);
                res.y = pcen_h(x[k].y, M, alpha, delta, dr);
                res.z = pcen_h(x[k].z, M, alpha, delta, dr);
                res.w = pcen_h(x[k].w, M, alpha, delta, dr);
            } else {
                res.x = pcen_g(x[k].x, M, alpha, r, delta, dr);
                res.y = pcen_g(x[k].y, M, alpha, r, delta, dr);
                res.z = pcen_g(x[k].z, M, alpha, r, delta, dr);
                res.w = pcen_g(x[k].w, M, alpha, r, delta, dr);
            }
            out4[rowBase4 + idx] = res;
        }
    }
}

__global__ __launch_bounds__(BLOCK, 6)
void pcen_kernel(const float4* __restrict__ data4,
                 const float*  __restrict__ alpha_p,
                 const float*  __restrict__ r_p,
                 const float*  __restrict__ delta_p,
                 float4* __restrict__ out4,
                 int T4, int wpr, int totalW)
{
    const int lane = threadIdx.x & 31;
    const int gw   = blockIdx.x * WARPS + (threadIdx.x >> 5);
    if (gw >= totalW) return;                        // warp-uniform

    const int row   = gw / wpr;
    const int slot  = gw - row * wpr;
    const int rowBase4 = row * T4;                   // int32 safe (< 12.8M)
    const int base4 = slot * SEG4;

    const float alpha = *alpha_p;
    const float r     = *r_p;
    const float delta = *delta_p;
    const bool  rhalf = (r == 0.5f);
    const float dr    = rhalf ? sqrta(delta) : ex2a(r * lg2a(delta));
    const float fl    = __uint_as_float((unsigned)(127 - 4 * lane) << 23); // 16^-lane

    const bool full = (base4 + SEG4) <= T4;

    if (full) {
        if (rhalf) do_segment<true,  true >(data4, out4, base4, lane, rowBase4, T4, alpha, r, delta, dr, fl);
        else       do_segment<true,  false>(data4, out4, base4, lane, rowBase4, T4, alpha, r, delta, dr, fl);
    } else {
        if (rhalf) do_segment<false, true >(data4, out4, base4, lane, rowBase4, T4, alpha, r, delta, dr, fl);
        else       do_segment<false, false>(data4, out4, base4, lane, rowBase4, T4, alpha, r, delta, dr, fl);
    }
}

extern "C" void kernel_launch(void* const* d_in, const int* in_sizes, int n_in,
                              void* d_out, int out_size)
{
    const float4* data4   = (const float4*)d_in[0];
    const float*  alpha_p = (const float*)d_in[1];
    const float*  r_p     = (const float*)d_in[2];
    const float*  delta_p = (const float*)d_in[3];
    float4* out4 = (float4*)d_out;

    const int total = in_sizes[0];
    const int F  = 1024;
    const int T  = total / F;                         // 50000
    const int T4 = T / 4;                             // 12500
    const int wpr    = (T4 + SEG4 - 1) / SEG4;        // 66 warps per row
    const int totalW = F * wpr;                       // 67584
    const int blocks = (totalW + WARPS - 1) / WARPS;  // 8448

    pcen_kernel<<<blocks, BLOCK>>>(data4, alpha_p, r_p, delta_p, out4,
                                   T4, wpr, totalW);
}